// round 8
// baseline (speedup 1.0000x reference)
#include <cuda_runtime.h>
#include <cuda_bf16.h>
#include <cstdint>
#include <cstddef>

#define NB 8
#define NC 512
#define NL 256
#define NP 4096
#define PLANE ((size_t)NL * NP)     // 1048576
#define BN_EPS 1e-5f
#define SIM_SCALE 0.0625f           // 256^-0.5

// bf16 scratch
__device__ __nv_bfloat16 g_wbf[3ull * 4 * NL * NC];        // [mat][s][l][c]
__device__ __nv_bfloat16 g_wubf[4ull * NC * NL];           // [s][c][m]
__device__ __nv_bfloat16 g_xbf[4ull * NB * NC * NP];       // [s][b][c][p]
__device__ __nv_bfloat16 g_kqvb[12ull * NB * PLANE];       // [mat*4+s][b][l][p]
__device__ __nv_bfloat16 g_ctxb[(size_t)4 * NB * NP * NL]; // [sb][r][m]

// ---------------- helpers ---------------------------------------------------
__device__ __forceinline__ uint32_t smem_u32(const void* p) {
    return (uint32_t)__cvta_generic_to_shared(p);
}
__device__ __forceinline__ void ldsm_x4(uint32_t& r0, uint32_t& r1,
                                        uint32_t& r2, uint32_t& r3, uint32_t a) {
    asm volatile("ldmatrix.sync.aligned.m8n8.x4.shared.b16 {%0,%1,%2,%3}, [%4];"
                 : "=r"(r0), "=r"(r1), "=r"(r2), "=r"(r3) : "r"(a));
}
__device__ __forceinline__ void ldsm_x4t(uint32_t& r0, uint32_t& r1,
                                         uint32_t& r2, uint32_t& r3, uint32_t a) {
    asm volatile("ldmatrix.sync.aligned.m8n8.x4.trans.shared.b16 {%0,%1,%2,%3}, [%4];"
                 : "=r"(r0), "=r"(r1), "=r"(r2), "=r"(r3) : "r"(a));
}
__device__ __forceinline__ void mma_bf16(float* c, const uint32_t* a,
                                         uint32_t b0, uint32_t b1) {
    asm volatile(
        "mma.sync.aligned.m16n8k16.row.col.f32.bf16.bf16.f32 "
        "{%0,%1,%2,%3},{%4,%5,%6,%7},{%8,%9},{%0,%1,%2,%3};"
        : "+f"(c[0]), "+f"(c[1]), "+f"(c[2]), "+f"(c[3])
        : "r"(a[0]), "r"(a[1]), "r"(a[2]), "r"(a[3]), "r"(b0), "r"(b1));
}
__device__ __forceinline__ void cp16(uint32_t dst, const void* src) {
    asm volatile("cp.async.cg.shared.global [%0], [%1], 16;" :: "r"(dst), "l"(src));
}
__device__ __forceinline__ void cp_commit() {
    asm volatile("cp.async.commit_group;");
}
template <int N>
__device__ __forceinline__ void cp_wait() {
    asm volatile("cp.async.wait_group %0;" :: "n"(N));
}

// ---------------- conversion kernels ----------------------------------------
__global__ void kconv_w(const float* __restrict__ Wk, const float* __restrict__ Wq,
                        const float* __restrict__ Wd, const float* __restrict__ Wu)
{
    const size_t i = (size_t)blockIdx.x * blockDim.x + threadIdx.x;
    const size_t nw = 4ull * NL * NC;       // 524288
    if (i < nw) {
        g_wbf[0 * nw + i] = __float2bfloat16(Wk[i]);
        g_wbf[1 * nw + i] = __float2bfloat16(Wq[i]);
        g_wbf[2 * nw + i] = __float2bfloat16(Wd[i]);
        g_wubf[i]         = __float2bfloat16(Wu[i]);
    }
}

__global__ void kconv_x(const float* __restrict__ x0, const float* __restrict__ x1,
                        const float* __restrict__ x2, const float* __restrict__ x3)
{
    const int s = blockIdx.y;
    const float* xp = (s == 0) ? x0 : (s == 1) ? x1 : (s == 2) ? x2 : x3;
    __nv_bfloat16* dst = g_xbf + (size_t)s * NB * NC * NP;
    const size_t n4 = (size_t)NB * NC * NP / 4;
    for (size_t i = (size_t)blockIdx.x * blockDim.x + threadIdx.x;
         i < n4; i += (size_t)gridDim.x * blockDim.x) {
        float4 v = *(const float4*)(xp + i * 4);
        __nv_bfloat162 lo = __floats2bfloat162_rn(v.x, v.y);
        __nv_bfloat162 hi = __floats2bfloat162_rn(v.z, v.w);
        uint2 pk;
        pk.x = *(uint32_t*)&lo;
        pk.y = *(uint32_t*)&hi;
        *(uint2*)(dst + i * 4) = pk;
    }
}

// ---------------- Kernel P: projection GEMM (tensor core, pipelined) --------
// C[l 256 x p 128] = W[256 x 512] * X[512 x p128] for one (mat,s,b).
// grid (32 ptiles, 12 = mat*4+s, 8 b), 256 threads, 8 warps (wm 0..3, wn 0..1),
// warp tile 64l x 64p. K chunks of 32, 2-stage cp.async double buffer.
#define SA 40    // Wsm row stride (bf16), 32 + 8 pad
#define SB 136   // Xsm row stride (bf16), 128 + 8 pad
#define KP_W_ELEMS (256 * SA)
#define KP_X_ELEMS (32 * SB)
#define KP_SMEM ((2 * KP_W_ELEMS + 2 * KP_X_ELEMS) * 2)

__global__ __launch_bounds__(256, 1)
void kp_proj(const float* __restrict__ bk,
             const float* __restrict__ gk, const float* __restrict__ betak,
             const float* __restrict__ mk, const float* __restrict__ vk,
             const float* __restrict__ bq,
             const float* __restrict__ gq, const float* __restrict__ betaq,
             const float* __restrict__ mq, const float* __restrict__ vq,
             const float* __restrict__ bd)
{
    extern __shared__ __nv_bfloat16 smp[];
    __nv_bfloat16* Wsm[2] = { smp, smp + KP_W_ELEMS };
    __nv_bfloat16* Xsm[2] = { smp + 2 * KP_W_ELEMS,
                              smp + 2 * KP_W_ELEMS + KP_X_ELEMS };

    const int p0  = blockIdx.x * 128;
    const int mat = blockIdx.y >> 2;
    const int s   = blockIdx.y & 3;
    const int b   = blockIdx.z;
    const int tid = threadIdx.x;
    const int warp = tid >> 5, lane = tid & 31;
    const int wm = warp >> 1, wn = warp & 1;

    const __nv_bfloat16* wsrc = g_wbf + ((size_t)mat * 4 + s) * (NL * NC);
    const __nv_bfloat16* xsrc = g_xbf + ((size_t)(s * NB + b)) * (NC * NP);

    // per-thread load coords
    const int wl_row = tid >> 2,  wl_c8 = (tid & 3) * 8;     // W: 4 iters stride 64 rows
    const int xl_row = tid >> 4,  xl_p8 = (tid & 15) * 8;    // X: 2 iters stride 16 rows

    auto issue = [&](int chunk, int buf) {
        const int c0 = chunk * 32;
        #pragma unroll
        for (int it = 0; it < 4; it++) {
            int row = wl_row + it * 64;
            cp16(smem_u32(Wsm[buf] + row * SA + wl_c8),
                 wsrc + (size_t)row * NC + c0 + wl_c8);
        }
        #pragma unroll
        for (int it = 0; it < 2; it++) {
            int row = xl_row + it * 16;
            cp16(smem_u32(Xsm[buf] + row * SB + xl_p8),
                 xsrc + (size_t)(c0 + row) * NP + p0 + xl_p8);
        }
        cp_commit();
    };

    float acc[4][8][4];
    #pragma unroll
    for (int i = 0; i < 4; i++)
        #pragma unroll
        for (int j = 0; j < 8; j++)
            #pragma unroll
            for (int r = 0; r < 4; r++) acc[i][j][r] = 0.f;

    issue(0, 0);

    #pragma unroll 1
    for (int c = 0; c < 16; c++) {
        const int cur = c & 1;
        if (c < 15) issue(c + 1, cur ^ 1);
        if (c < 15) cp_wait<1>(); else cp_wait<0>();
        __syncthreads();

        const uint32_t wbase = smem_u32(Wsm[cur]);
        const uint32_t xbase = smem_u32(Xsm[cur]);
        #pragma unroll
        for (int k0 = 0; k0 < 32; k0 += 16) {
            uint32_t a[4][4];
            #pragma unroll
            for (int mt = 0; mt < 4; mt++) {
                uint32_t addr = wbase +
                    ((wm * 64 + mt * 16 + (lane & 15)) * SA + k0 + ((lane & 16) >> 1)) * 2;
                ldsm_x4(a[mt][0], a[mt][1], a[mt][2], a[mt][3], addr);
            }
            uint32_t bb[8][2];
            #pragma unroll
            for (int ntp = 0; ntp < 4; ntp++) {
                uint32_t addr = xbase +
                    ((k0 + (lane & 15)) * SB + wn * 64 + ntp * 16 + ((lane & 16) >> 1)) * 2;
                uint32_t r0, r1, r2, r3;
                ldsm_x4t(r0, r1, r2, r3, addr);
                bb[ntp * 2 + 0][0] = r0; bb[ntp * 2 + 0][1] = r1;
                bb[ntp * 2 + 1][0] = r2; bb[ntp * 2 + 1][1] = r3;
            }
            #pragma unroll
            for (int mt = 0; mt < 4; mt++)
                #pragma unroll
                for (int nt = 0; nt < 8; nt++)
                    mma_bf16(acc[mt][nt], a[mt], bb[nt][0], bb[nt][1]);
        }
        __syncthreads();
    }

    // epilogue: BN/bias per l, write bf16 plane [l][p]
    __nv_bfloat16* plane = g_kqvb + (((size_t)(mat * 4 + s)) * NB + b) * PLANE;
    #pragma unroll
    for (int mt = 0; mt < 4; mt++)
        #pragma unroll
        for (int half = 0; half < 2; half++) {
            const int l  = wm * 64 + mt * 16 + (lane >> 2) + half * 8;
            const int sl = s * NL + l;
            float sc, sh;
            if (mat == 0) {
                sc = __ldg(gk + sl) * rsqrtf(__ldg(vk + sl) + BN_EPS);
                sh = __ldg(betak + sl) + (__ldg(bk + sl) - __ldg(mk + sl)) * sc;
            } else if (mat == 1) {
                sc = __ldg(gq + sl) * rsqrtf(__ldg(vq + sl) + BN_EPS);
                sh = __ldg(betaq + sl) + (__ldg(bq + sl) - __ldg(mq + sl)) * sc;
            } else {
                sc = 1.f;
                sh = __ldg(bd + sl);
            }
            #pragma unroll
            for (int nt = 0; nt < 8; nt++) {
                const int p = p0 + wn * 64 + nt * 8 + (lane & 3) * 2;
                float v0 = acc[mt][nt][half * 2 + 0];
                float v1 = acc[mt][nt][half * 2 + 1];
                v0 = fmaf(v0, sc, sh);
                v1 = fmaf(v1, sc, sh);
                if (mat < 2) { v0 = fmaxf(v0, 0.f); v1 = fmaxf(v1, 0.f); }
                __nv_bfloat162 pk = __floats2bfloat162_rn(v0, v1);
                *(uint32_t*)(plane + (size_t)l * NP + p) = *(uint32_t*)&pk;
            }
        }
}

// ---------------- Kernel A: per-position 4x4 stream attention ---------------
__global__ __launch_bounds__(256)
void ka_attn()
{
    const int b    = blockIdx.y;
    const int warp = threadIdx.x >> 5;
    const int lane = threadIdx.x & 31;
    const int r    = blockIdx.x * 8 + warp;

    float2 qv[4][4], kv[4][4], vv[4][4];
    #pragma unroll
    for (int s = 0; s < 4; s++) {
        const __nv_bfloat162* kb = (const __nv_bfloat162*)
            (g_kqvb + (((size_t)(0 * 4 + s)) * NB + b) * PLANE + (size_t)r * NL);
        const __nv_bfloat162* qb = (const __nv_bfloat162*)
            (g_kqvb + (((size_t)(1 * 4 + s)) * NB + b) * PLANE + (size_t)r * NL);
        const __nv_bfloat162* vb = (const __nv_bfloat162*)
            (g_kqvb + (((size_t)(2 * 4 + s)) * NB + b) * PLANE + (size_t)r * NL);
        #pragma unroll
        for (int e = 0; e < 4; e++) {
            kv[s][e] = __bfloat1622float2(kb[lane + e * 32]);
            qv[s][e] = __bfloat1622float2(qb[lane + e * 32]);
            vv[s][e] = __bfloat1622float2(vb[lane + e * 32]);
        }
    }
    float sim[4][4];
    #pragma unroll
    for (int s = 0; s < 4; s++)
        #pragma unroll
        for (int t = 0; t < 4; t++) {
            float p = 0.f;
            #pragma unroll
            for (int e = 0; e < 4; e++) {
                p = fmaf(qv[s][e].x, kv[t][e].x, p);
                p = fmaf(qv[s][e].y, kv[t][e].y, p);
            }
            #pragma unroll
            for (int off = 16; off > 0; off >>= 1)
                p += __shfl_xor_sync(0xffffffffu, p, off);
            sim[s][t] = p * SIM_SCALE;
        }
    float attn[4][4];
    #pragma unroll
    for (int s = 0; s < 4; s++) {
        float mx = fmaxf(fmaxf(sim[s][0], sim[s][1]), fmaxf(sim[s][2], sim[s][3]));
        float e0 = __expf(sim[s][0] - mx);
        float e1 = __expf(sim[s][1] - mx);
        float e2 = __expf(sim[s][2] - mx);
        float e3 = __expf(sim[s][3] - mx);
        float inv = 1.f / (e0 + e1 + e2 + e3);
        attn[s][0] = e0 * inv; attn[s][1] = e1 * inv;
        attn[s][2] = e2 * inv; attn[s][3] = e3 * inv;
    }
    #pragma unroll
    for (int s = 0; s < 4; s++) {
        __nv_bfloat162* dst = (__nv_bfloat162*)
            (g_ctxb + (((size_t)(s * NB + b)) * NP + r) * NL);
        #pragma unroll
        for (int e = 0; e < 4; e++) {
            float cx = attn[s][0] * vv[0][e].x + attn[s][1] * vv[1][e].x
                     + attn[s][2] * vv[2][e].x + attn[s][3] * vv[3][e].x;
            float cy = attn[s][0] * vv[0][e].y + attn[s][1] * vv[1][e].y
                     + attn[s][2] * vv[2][e].y + attn[s][3] * vv[3][e].y;
            dst[lane + e * 32] = __floats2bfloat162_rn(cx, cy);
        }
    }
}

// ---------------- Kernel U: up-projection + bias + residual (pipelined) -----
// grid (32 ptiles, 4 ctiles, 32 sb), 256 thr (8 warps 2x4), 2-stage cp.async.
#define SC 40
#define KU_T_ELEMS (128 * SC)

__global__ __launch_bounds__(256, 1)
void ku_up(const float* __restrict__ x0, const float* __restrict__ x1,
           const float* __restrict__ x2, const float* __restrict__ x3,
           const float* __restrict__ bu, float* __restrict__ out)
{
    extern __shared__ __nv_bfloat16 smu[];
    __nv_bfloat16* Wsm[2] = { smu, smu + KU_T_ELEMS };
    __nv_bfloat16* Csm[2] = { smu + 2 * KU_T_ELEMS, smu + 3 * KU_T_ELEMS };

    const int sb = blockIdx.z;
    const int s  = sb >> 3;
    const int b  = sb & 7;
    const int c0b = blockIdx.y * 128;
    const int p0  = blockIdx.x * 128;
    const int tid = threadIdx.x;
    const int warp = tid >> 5, lane = tid & 31;
    const int wm = warp >> 2, wn = warp & 3;

    const __nv_bfloat16* wsrc = g_wubf + ((size_t)s * NC + c0b) * NL;
    const __nv_bfloat16* csrc = g_ctxb + ((size_t)sb * NP + p0) * NL;

    const int l_row = tid >> 1, l_m8 = (tid & 1) * 8;   // 2 iters stride... 128 rows/256thr

    auto issue = [&](int chunk, int buf) {
        const int m0 = chunk * 32;
        #pragma unroll
        for (int it = 0; it < 2; it++) {
            int f = it * 256 + tid;
            int row = f >> 2, m8 = (f & 3) * 8;
            cp16(smem_u32(Wsm[buf] + row * SC + m8),
                 wsrc + (size_t)row * NL + m0 + m8);
            cp16(smem_u32(Csm[buf] + row * SC + m8),
                 csrc + (size_t)row * NL + m0 + m8);
        }
        cp_commit();
    };
    (void)l_row; (void)l_m8;

    float acc[4][4][4];
    #pragma unroll
    for (int i = 0; i < 4; i++)
        #pragma unroll
        for (int j = 0; j < 4; j++)
            #pragma unroll
            for (int r = 0; r < 4; r++) acc[i][j][r] = 0.f;

    issue(0, 0);

    #pragma unroll 1
    for (int c = 0; c < 8; c++) {
        const int cur = c & 1;
        if (c < 7) issue(c + 1, cur ^ 1);
        if (c < 7) cp_wait<1>(); else cp_wait<0>();
        __syncthreads();

        const uint32_t wbase = smem_u32(Wsm[cur]);
        const uint32_t cbase = smem_u32(Csm[cur]);
        #pragma unroll
        for (int k0 = 0; k0 < 32; k0 += 16) {
            uint32_t a[4][4];
            #pragma unroll
            for (int mt = 0; mt < 4; mt++) {
                uint32_t addr = wbase +
                    ((wm * 64 + mt * 16 + (lane & 15)) * SC + k0 + ((lane & 16) >> 1)) * 2;
                ldsm_x4(a[mt][0], a[mt][1], a[mt][2], a[mt][3], addr);
            }
            uint32_t bb[4][2];
            #pragma unroll
            for (int ntp = 0; ntp < 2; ntp++) {
                uint32_t addr = cbase +
                    ((wn * 32 + ntp * 16 + (lane & 7) + ((lane & 16) >> 1)) * SC
                     + k0 + (lane & 8)) * 2;
                uint32_t r0, r1, r2, r3;
                ldsm_x4(r0, r1, r2, r3, addr);
                bb[ntp * 2 + 0][0] = r0; bb[ntp * 2 + 0][1] = r1;
                bb[ntp * 2 + 1][0] = r2; bb[ntp * 2 + 1][1] = r3;
            }
            #pragma unroll
            for (int mt = 0; mt < 4; mt++)
                #pragma unroll
                for (int nt = 0; nt < 4; nt++)
                    mma_bf16(acc[mt][nt], a[mt], bb[nt][0], bb[nt][1]);
        }
        __syncthreads();
    }

    const float* xp = (s == 0) ? x0 : (s == 1) ? x1 : (s == 2) ? x2 : x3;
    #pragma unroll
    for (int mt = 0; mt < 4; mt++)
        #pragma unroll
        for (int half = 0; half < 2; half++) {
            const int c = c0b + wm * 64 + mt * 16 + (lane >> 2) + half * 8;
            const float bias = __ldg(bu + s * NC + c);
            const float* xrow = xp + ((size_t)b * NC + c) * NP + p0;
            float* orow = out + ((size_t)sb * NC + c) * NP + p0;
            #pragma unroll
            for (int nt = 0; nt < 4; nt++) {
                const int p = wn * 32 + nt * 8 + (lane & 3) * 2;
                float2 xv = *(const float2*)(xrow + p);
                float2 o;
                o.x = xv.x + bias + acc[mt][nt][half * 2 + 0];
                o.y = xv.y + bias + acc[mt][nt][half * 2 + 1];
                *(float2*)(orow + p) = o;
            }
        }
}

extern "C" void kernel_launch(void* const* d_in, const int* in_sizes, int n_in,
                              void* d_out, int out_size)
{
    const float* x0    = (const float*)d_in[0];
    const float* x1    = (const float*)d_in[1];
    const float* x2    = (const float*)d_in[2];
    const float* x3    = (const float*)d_in[3];
    const float* Wk    = (const float*)d_in[4];
    const float* bk    = (const float*)d_in[5];
    const float* gk    = (const float*)d_in[6];
    const float* betak = (const float*)d_in[7];
    const float* mk    = (const float*)d_in[8];
    const float* vk    = (const float*)d_in[9];
    const float* Wq    = (const float*)d_in[10];
    const float* bq    = (const float*)d_in[11];
    const float* gq    = (const float*)d_in[12];
    const float* betaq = (const float*)d_in[13];
    const float* mq    = (const float*)d_in[14];
    const float* vq    = (const float*)d_in[15];
    const float* Wd    = (const float*)d_in[16];
    const float* bd    = (const float*)d_in[17];
    const float* Wu    = (const float*)d_in[18];
    const float* bu    = (const float*)d_in[19];
    float* out = (float*)d_out;

    static bool attr_done = false;
    if (!attr_done) {
        cudaFuncSetAttribute(kp_proj, cudaFuncAttributeMaxDynamicSharedMemorySize, KP_SMEM);
        cudaFuncSetAttribute(ku_up,   cudaFuncAttributeMaxDynamicSharedMemorySize,
                             4 * KU_T_ELEMS * 2);
        attr_done = true;
    }

    kconv_w<<<2048, 256>>>(Wk, Wq, Wd, Wu);
    kconv_x<<<dim3(4096, 4), 256>>>(x0, x1, x2, x3);
    kp_proj<<<dim3(32, 12, 8), 256, KP_SMEM>>>(bk, gk, betak, mk, vk,
                                               bq, gq, betaq, mq, vq, bd);
    ka_attn<<<dim3(512, 8), 256>>>();
    ku_up<<<dim3(32, 4, 32), 256, 4 * KU_T_ELEMS * 2>>>(x0, x1, x2, x3, bu, out);
}

// round 9
// speedup vs baseline: 1.2426x; 1.2426x over previous
#include <cuda_runtime.h>
#include <cuda_bf16.h>
#include <cstdint>
#include <cstddef>

#define NB 8
#define NC 512
#define NL 256
#define NP 4096
#define PLANE ((size_t)NL * NP)     // 1048576
#define BN_EPS 1e-5f
#define SIM_SCALE 0.0625f           // 256^-0.5

// bf16 scratch
__device__ __nv_bfloat16 g_wbf[3ull * 4 * NL * NC];        // [mat][s][l][c]
__device__ __nv_bfloat16 g_wubf[4ull * NC * NL];           // [s][c][m]
__device__ __nv_bfloat16 g_xbf[4ull * NB * NC * NP];       // [s][b][c][p]
__device__ __nv_bfloat16 g_kqvb[12ull * NB * PLANE];       // [mat*4+s][b][l][p]
__device__ __nv_bfloat16 g_ctxb[(size_t)4 * NB * NP * NL]; // [sb][r][m]

// ---------------- helpers ---------------------------------------------------
__device__ __forceinline__ uint32_t smem_u32(const void* p) {
    return (uint32_t)__cvta_generic_to_shared(p);
}
__device__ __forceinline__ void ldsm_x4(uint32_t& r0, uint32_t& r1,
                                        uint32_t& r2, uint32_t& r3, uint32_t a) {
    asm volatile("ldmatrix.sync.aligned.m8n8.x4.shared.b16 {%0,%1,%2,%3}, [%4];"
                 : "=r"(r0), "=r"(r1), "=r"(r2), "=r"(r3) : "r"(a));
}
__device__ __forceinline__ void ldsm_x4t(uint32_t& r0, uint32_t& r1,
                                         uint32_t& r2, uint32_t& r3, uint32_t a) {
    asm volatile("ldmatrix.sync.aligned.m8n8.x4.trans.shared.b16 {%0,%1,%2,%3}, [%4];"
                 : "=r"(r0), "=r"(r1), "=r"(r2), "=r"(r3) : "r"(a));
}
__device__ __forceinline__ void mma_bf16(float* c, const uint32_t* a,
                                         uint32_t b0, uint32_t b1) {
    asm volatile(
        "mma.sync.aligned.m16n8k16.row.col.f32.bf16.bf16.f32 "
        "{%0,%1,%2,%3},{%4,%5,%6,%7},{%8,%9},{%0,%1,%2,%3};"
        : "+f"(c[0]), "+f"(c[1]), "+f"(c[2]), "+f"(c[3])
        : "r"(a[0]), "r"(a[1]), "r"(a[2]), "r"(a[3]), "r"(b0), "r"(b1));
}
__device__ __forceinline__ void cp16(uint32_t dst, const void* src) {
    asm volatile("cp.async.cg.shared.global [%0], [%1], 16;" :: "r"(dst), "l"(src));
}
__device__ __forceinline__ void cp_commit() {
    asm volatile("cp.async.commit_group;");
}
template <int N>
__device__ __forceinline__ void cp_wait() {
    asm volatile("cp.async.wait_group %0;" :: "n"(N));
}

// ---------------- conversion kernels ----------------------------------------
__global__ void kconv_w(const float* __restrict__ Wk, const float* __restrict__ Wq,
                        const float* __restrict__ Wd, const float* __restrict__ Wu)
{
    const size_t i = (size_t)blockIdx.x * blockDim.x + threadIdx.x;
    const size_t nw = 4ull * NL * NC;       // 524288
    if (i < nw) {
        g_wbf[0 * nw + i] = __float2bfloat16(Wk[i]);
        g_wbf[1 * nw + i] = __float2bfloat16(Wq[i]);
        g_wbf[2 * nw + i] = __float2bfloat16(Wd[i]);
        g_wubf[i]         = __float2bfloat16(Wu[i]);
    }
}

__global__ void kconv_x(const float* __restrict__ x0, const float* __restrict__ x1,
                        const float* __restrict__ x2, const float* __restrict__ x3)
{
    const int s = blockIdx.y;
    const float* xp = (s == 0) ? x0 : (s == 1) ? x1 : (s == 2) ? x2 : x3;
    __nv_bfloat16* dst = g_xbf + (size_t)s * NB * NC * NP;
    const size_t n4 = (size_t)NB * NC * NP / 4;
    for (size_t i = (size_t)blockIdx.x * blockDim.x + threadIdx.x;
         i < n4; i += (size_t)gridDim.x * blockDim.x) {
        float4 v = *(const float4*)(xp + i * 4);
        __nv_bfloat162 lo = __floats2bfloat162_rn(v.x, v.y);
        __nv_bfloat162 hi = __floats2bfloat162_rn(v.z, v.w);
        uint2 pk;
        pk.x = *(uint32_t*)&lo;
        pk.y = *(uint32_t*)&hi;
        *(uint2*)(dst + i * 4) = pk;
    }
}

// ---------------- Kernel P: projection GEMM (tensor core, 2-stage pipe) -----
// C[l 128 x p 128] = W[l x 512] * X[512 x p] for one (mat,s,b,ltile).
// grid (32 ptiles, 12 = mat*4+s, 16 = b*2+ltile), 256 threads (8 warps 2x4).
#define SA 40    // Wsm row stride (bf16), 32 + 8 pad
#define SB 136   // Xsm row stride (bf16), 128 + 8 pad

__global__ __launch_bounds__(256)
void kp_proj(const float* __restrict__ bk,
             const float* __restrict__ gk, const float* __restrict__ betak,
             const float* __restrict__ mk, const float* __restrict__ vk,
             const float* __restrict__ bq,
             const float* __restrict__ gq, const float* __restrict__ betaq,
             const float* __restrict__ mq, const float* __restrict__ vq,
             const float* __restrict__ bd)
{
    __shared__ __nv_bfloat16 Wsm[2][128 * SA];
    __shared__ __nv_bfloat16 Xsm[2][32 * SB];

    const int p0  = blockIdx.x * 128;
    const int mat = blockIdx.y >> 2;
    const int s   = blockIdx.y & 3;
    const int b   = blockIdx.z >> 1;
    const int l0  = (blockIdx.z & 1) * 128;
    const int tid = threadIdx.x;
    const int warp = tid >> 5, lane = tid & 31;
    const int wm = warp >> 2, wn = warp & 3;

    const __nv_bfloat16* wsrc = g_wbf + ((size_t)mat * 4 + s) * (NL * NC)
                                      + (size_t)l0 * NC;
    const __nv_bfloat16* xsrc = g_xbf + ((size_t)(s * NB + b)) * (NC * NP);

    // per-thread load coords (2 iters each of W and X)
    const int wl_row = tid >> 2,  wl_c8 = (tid & 3) * 8;   // W rows 0..63, +64
    const int xl_row = tid >> 4,  xl_p8 = (tid & 15) * 8;  // X rows 0..15, +16

    auto issue = [&](int chunk, int buf) {
        const int c0 = chunk * 32;
        cp16(smem_u32(&Wsm[buf][wl_row * SA + wl_c8]),
             wsrc + (size_t)wl_row * NC + c0 + wl_c8);
        cp16(smem_u32(&Wsm[buf][(wl_row + 64) * SA + wl_c8]),
             wsrc + (size_t)(wl_row + 64) * NC + c0 + wl_c8);
        cp16(smem_u32(&Xsm[buf][xl_row * SB + xl_p8]),
             xsrc + (size_t)(c0 + xl_row) * NP + p0 + xl_p8);
        cp16(smem_u32(&Xsm[buf][(xl_row + 16) * SB + xl_p8]),
             xsrc + (size_t)(c0 + xl_row + 16) * NP + p0 + xl_p8);
        cp_commit();
    };

    float acc[4][4][4];
    #pragma unroll
    for (int i = 0; i < 4; i++)
        #pragma unroll
        for (int j = 0; j < 4; j++)
            #pragma unroll
            for (int r = 0; r < 4; r++) acc[i][j][r] = 0.f;

    issue(0, 0);

    #pragma unroll 1
    for (int c = 0; c < 16; c++) {
        const int cur = c & 1;
        if (c < 15) { issue(c + 1, cur ^ 1); cp_wait<1>(); }
        else        { cp_wait<0>(); }
        __syncthreads();

        const uint32_t wbase = smem_u32(Wsm[cur]);
        const uint32_t xbase = smem_u32(Xsm[cur]);
        #pragma unroll
        for (int k0 = 0; k0 < 32; k0 += 16) {
            uint32_t a[4][4];
            #pragma unroll
            for (int mt = 0; mt < 4; mt++) {
                uint32_t addr = wbase +
                    ((wm * 64 + mt * 16 + (lane & 15)) * SA + k0 + ((lane & 16) >> 1)) * 2;
                ldsm_x4(a[mt][0], a[mt][1], a[mt][2], a[mt][3], addr);
            }
            uint32_t bb[4][2];
            #pragma unroll
            for (int ntp = 0; ntp < 2; ntp++) {
                uint32_t addr = xbase +
                    ((k0 + (lane & 15)) * SB + wn * 32 + ntp * 16 + ((lane & 16) >> 1)) * 2;
                uint32_t r0, r1, r2, r3;
                ldsm_x4t(r0, r1, r2, r3, addr);
                bb[ntp * 2 + 0][0] = r0; bb[ntp * 2 + 0][1] = r1;
                bb[ntp * 2 + 1][0] = r2; bb[ntp * 2 + 1][1] = r3;
            }
            #pragma unroll
            for (int mt = 0; mt < 4; mt++)
                #pragma unroll
                for (int nt = 0; nt < 4; nt++)
                    mma_bf16(acc[mt][nt], a[mt], bb[nt][0], bb[nt][1]);
        }
        __syncthreads();
    }

    // epilogue: BN/bias per l, write bf16 plane [l][p]
    __nv_bfloat16* plane = g_kqvb + (((size_t)(mat * 4 + s)) * NB + b) * PLANE;
    #pragma unroll
    for (int mt = 0; mt < 4; mt++)
        #pragma unroll
        for (int half = 0; half < 2; half++) {
            const int l  = l0 + wm * 64 + mt * 16 + (lane >> 2) + half * 8;
            const int sl = s * NL + l;
            float sc, sh;
            if (mat == 0) {
                sc = __ldg(gk + sl) * rsqrtf(__ldg(vk + sl) + BN_EPS);
                sh = __ldg(betak + sl) + (__ldg(bk + sl) - __ldg(mk + sl)) * sc;
            } else if (mat == 1) {
                sc = __ldg(gq + sl) * rsqrtf(__ldg(vq + sl) + BN_EPS);
                sh = __ldg(betaq + sl) + (__ldg(bq + sl) - __ldg(mq + sl)) * sc;
            } else {
                sc = 1.f;
                sh = __ldg(bd + sl);
            }
            #pragma unroll
            for (int nt = 0; nt < 4; nt++) {
                const int p = p0 + wn * 32 + nt * 8 + (lane & 3) * 2;
                float v0 = acc[mt][nt][half * 2 + 0];
                float v1 = acc[mt][nt][half * 2 + 1];
                v0 = fmaf(v0, sc, sh);
                v1 = fmaf(v1, sc, sh);
                if (mat < 2) { v0 = fmaxf(v0, 0.f); v1 = fmaxf(v1, 0.f); }
                __nv_bfloat162 pk = __floats2bfloat162_rn(v0, v1);
                *(uint32_t*)(plane + (size_t)l * NP + p) = *(uint32_t*)&pk;
            }
        }
}

// ---------------- Kernel A: per-position 4x4 stream attention ---------------
__global__ __launch_bounds__(256)
void ka_attn()
{
    const int b    = blockIdx.y;
    const int warp = threadIdx.x >> 5;
    const int lane = threadIdx.x & 31;
    const int r    = blockIdx.x * 8 + warp;

    float2 qv[4][4], kv[4][4], vv[4][4];
    #pragma unroll
    for (int s = 0; s < 4; s++) {
        const __nv_bfloat162* kb = (const __nv_bfloat162*)
            (g_kqvb + (((size_t)(0 * 4 + s)) * NB + b) * PLANE + (size_t)r * NL);
        const __nv_bfloat162* qb = (const __nv_bfloat162*)
            (g_kqvb + (((size_t)(1 * 4 + s)) * NB + b) * PLANE + (size_t)r * NL);
        const __nv_bfloat162* vb = (const __nv_bfloat162*)
            (g_kqvb + (((size_t)(2 * 4 + s)) * NB + b) * PLANE + (size_t)r * NL);
        #pragma unroll
        for (int e = 0; e < 4; e++) {
            kv[s][e] = __bfloat1622float2(kb[lane + e * 32]);
            qv[s][e] = __bfloat1622float2(qb[lane + e * 32]);
            vv[s][e] = __bfloat1622float2(vb[lane + e * 32]);
        }
    }
    float sim[4][4];
    #pragma unroll
    for (int s = 0; s < 4; s++)
        #pragma unroll
        for (int t = 0; t < 4; t++) {
            float p = 0.f;
            #pragma unroll
            for (int e = 0; e < 4; e++) {
                p = fmaf(qv[s][e].x, kv[t][e].x, p);
                p = fmaf(qv[s][e].y, kv[t][e].y, p);
            }
            #pragma unroll
            for (int off = 16; off > 0; off >>= 1)
                p += __shfl_xor_sync(0xffffffffu, p, off);
            sim[s][t] = p * SIM_SCALE;
        }
    float attn[4][4];
    #pragma unroll
    for (int s = 0; s < 4; s++) {
        float mx = fmaxf(fmaxf(sim[s][0], sim[s][1]), fmaxf(sim[s][2], sim[s][3]));
        float e0 = __expf(sim[s][0] - mx);
        float e1 = __expf(sim[s][1] - mx);
        float e2 = __expf(sim[s][2] - mx);
        float e3 = __expf(sim[s][3] - mx);
        float inv = 1.f / (e0 + e1 + e2 + e3);
        attn[s][0] = e0 * inv; attn[s][1] = e1 * inv;
        attn[s][2] = e2 * inv; attn[s][3] = e3 * inv;
    }
    #pragma unroll
    for (int s = 0; s < 4; s++) {
        __nv_bfloat162* dst = (__nv_bfloat162*)
            (g_ctxb + (((size_t)(s * NB + b)) * NP + r) * NL);
        #pragma unroll
        for (int e = 0; e < 4; e++) {
            float cx = attn[s][0] * vv[0][e].x + attn[s][1] * vv[1][e].x
                     + attn[s][2] * vv[2][e].x + attn[s][3] * vv[3][e].x;
            float cy = attn[s][0] * vv[0][e].y + attn[s][1] * vv[1][e].y
                     + attn[s][2] * vv[2][e].y + attn[s][3] * vv[3][e].y;
            dst[lane + e * 32] = __floats2bfloat162_rn(cx, cy);
        }
    }
}

// ---------------- Kernel U: up-projection + bias + residual (2-stage pipe) --
// grid (32 ptiles, 4 ctiles, 32 sb), 256 thr (8 warps 2x4).
#define SC 40

__global__ __launch_bounds__(256)
void ku_up(const float* __restrict__ x0, const float* __restrict__ x1,
           const float* __restrict__ x2, const float* __restrict__ x3,
           const float* __restrict__ bu, float* __restrict__ out)
{
    __shared__ __nv_bfloat16 Wsm[2][128 * SC];
    __shared__ __nv_bfloat16 Csm[2][128 * SC];

    const int sb = blockIdx.z;
    const int s  = sb >> 3;
    const int b  = sb & 7;
    const int c0b = blockIdx.y * 128;
    const int p0  = blockIdx.x * 128;
    const int tid = threadIdx.x;
    const int warp = tid >> 5, lane = tid & 31;
    const int wm = warp >> 2, wn = warp & 3;

    const __nv_bfloat16* wsrc = g_wubf + ((size_t)s * NC + c0b) * NL;
    const __nv_bfloat16* csrc = g_ctxb + ((size_t)sb * NP + p0) * NL;

    const int t_row = tid >> 2, t_m8 = (tid & 3) * 8;   // rows 0..63, +64

    auto issue = [&](int chunk, int buf) {
        const int m0 = chunk * 32;
        cp16(smem_u32(&Wsm[buf][t_row * SC + t_m8]),
             wsrc + (size_t)t_row * NL + m0 + t_m8);
        cp16(smem_u32(&Wsm[buf][(t_row + 64) * SC + t_m8]),
             wsrc + (size_t)(t_row + 64) * NL + m0 + t_m8);
        cp16(smem_u32(&Csm[buf][t_row * SC + t_m8]),
             csrc + (size_t)t_row * NL + m0 + t_m8);
        cp16(smem_u32(&Csm[buf][(t_row + 64) * SC + t_m8]),
             csrc + (size_t)(t_row + 64) * NL + m0 + t_m8);
        cp_commit();
    };

    float acc[4][4][4];
    #pragma unroll
    for (int i = 0; i < 4; i++)
        #pragma unroll
        for (int j = 0; j < 4; j++)
            #pragma unroll
            for (int r = 0; r < 4; r++) acc[i][j][r] = 0.f;

    issue(0, 0);

    #pragma unroll 1
    for (int c = 0; c < 8; c++) {
        const int cur = c & 1;
        if (c < 7) { issue(c + 1, cur ^ 1); cp_wait<1>(); }
        else       { cp_wait<0>(); }
        __syncthreads();

        const uint32_t wbase = smem_u32(Wsm[cur]);
        const uint32_t cbase = smem_u32(Csm[cur]);
        #pragma unroll
        for (int k0 = 0; k0 < 32; k0 += 16) {
            uint32_t a[4][4];
            #pragma unroll
            for (int mt = 0; mt < 4; mt++) {
                uint32_t addr = wbase +
                    ((wm * 64 + mt * 16 + (lane & 15)) * SC + k0 + ((lane & 16) >> 1)) * 2;
                ldsm_x4(a[mt][0], a[mt][1], a[mt][2], a[mt][3], addr);
            }
            uint32_t bb[4][2];
            #pragma unroll
            for (int ntp = 0; ntp < 2; ntp++) {
                uint32_t addr = cbase +
                    ((wn * 32 + ntp * 16 + (lane & 7) + ((lane & 16) >> 1)) * SC
                     + k0 + (lane & 8)) * 2;
                uint32_t r0, r1, r2, r3;
                ldsm_x4(r0, r1, r2, r3, addr);
                bb[ntp * 2 + 0][0] = r0; bb[ntp * 2 + 0][1] = r1;
                bb[ntp * 2 + 1][0] = r2; bb[ntp * 2 + 1][1] = r3;
            }
            #pragma unroll
            for (int mt = 0; mt < 4; mt++)
                #pragma unroll
                for (int nt = 0; nt < 4; nt++)
                    mma_bf16(acc[mt][nt], a[mt], bb[nt][0], bb[nt][1]);
        }
        __syncthreads();
    }

    const float* xp = (s == 0) ? x0 : (s == 1) ? x1 : (s == 2) ? x2 : x3;
    #pragma unroll
    for (int mt = 0; mt < 4; mt++)
        #pragma unroll
        for (int half = 0; half < 2; half++) {
            const int c = c0b + wm * 64 + mt * 16 + (lane >> 2) + half * 8;
            const float bias = __ldg(bu + s * NC + c);
            const float* xrow = xp + ((size_t)b * NC + c) * NP + p0;
            float* orow = out + ((size_t)sb * NC + c) * NP + p0;
            #pragma unroll
            for (int nt = 0; nt < 4; nt++) {
                const int p = wn * 32 + nt * 8 + (lane & 3) * 2;
                float2 xv = *(const float2*)(xrow + p);
                float2 o;
                o.x = xv.x + bias + acc[mt][nt][half * 2 + 0];
                o.y = xv.y + bias + acc[mt][nt][half * 2 + 1];
                *(float2*)(orow + p) = o;
            }
        }
}

extern "C" void kernel_launch(void* const* d_in, const int* in_sizes, int n_in,
                              void* d_out, int out_size)
{
    const float* x0    = (const float*)d_in[0];
    const float* x1    = (const float*)d_in[1];
    const float* x2    = (const float*)d_in[2];
    const float* x3    = (const float*)d_in[3];
    const float* Wk    = (const float*)d_in[4];
    const float* bk    = (const float*)d_in[5];
    const float* gk    = (const float*)d_in[6];
    const float* betak = (const float*)d_in[7];
    const float* mk    = (const float*)d_in[8];
    const float* vk    = (const float*)d_in[9];
    const float* Wq    = (const float*)d_in[10];
    const float* bq    = (const float*)d_in[11];
    const float* gq    = (const float*)d_in[12];
    const float* betaq = (const float*)d_in[13];
    const float* mq    = (const float*)d_in[14];
    const float* vq    = (const float*)d_in[15];
    const float* Wd    = (const float*)d_in[16];
    const float* bd    = (const float*)d_in[17];
    const float* Wu    = (const float*)d_in[18];
    const float* bu    = (const float*)d_in[19];
    float* out = (float*)d_out;

    kconv_w<<<2048, 256>>>(Wk, Wq, Wd, Wu);
    kconv_x<<<dim3(4096, 4), 256>>>(x0, x1, x2, x3);
    kp_proj<<<dim3(32, 12, 16), 256>>>(bk, gk, betak, mk, vk,
                                       bq, gq, betaq, mq, vq, bd);
    ka_attn<<<dim3(512, 8), 256>>>();
    ku_up<<<dim3(32, 4, 32), 256>>>(x0, x1, x2, x3, bu, out);
}

// round 10
// speedup vs baseline: 1.2428x; 1.0001x over previous
#include <cuda_runtime.h>
#include <cuda_bf16.h>
#include <cstdint>
#include <cstddef>

#define NB 8
#define NC 512
#define NL 256
#define NP 4096
#define PLANE ((size_t)NL * NP)     // 1048576
#define BN_EPS 1e-5f
#define SIM_SCALE 0.0625f           // 256^-0.5

// bf16 scratch
__device__ __nv_bfloat16 g_wbf[3ull * 4 * NL * NC];        // [mat][s][l][c]
__device__ __nv_bfloat16 g_wubf[4ull * NC * NL];           // [s][c][m]
__device__ __nv_bfloat16 g_xbf[4ull * NB * NC * NP];       // [s][b][c][p]
__device__ __nv_bfloat16 g_kqvb[12ull * NB * PLANE];       // [mat*4+s][b][l][p]
__device__ __nv_bfloat16 g_ctxb[(size_t)4 * NB * NP * NL]; // [sb][r][m]

// ---------------- helpers ---------------------------------------------------
__device__ __forceinline__ uint32_t smem_u32(const void* p) {
    return (uint32_t)__cvta_generic_to_shared(p);
}
__device__ __forceinline__ void ldsm_x4(uint32_t& r0, uint32_t& r1,
                                        uint32_t& r2, uint32_t& r3, uint32_t a) {
    asm volatile("ldmatrix.sync.aligned.m8n8.x4.shared.b16 {%0,%1,%2,%3}, [%4];"
                 : "=r"(r0), "=r"(r1), "=r"(r2), "=r"(r3) : "r"(a));
}
__device__ __forceinline__ void ldsm_x4t(uint32_t& r0, uint32_t& r1,
                                         uint32_t& r2, uint32_t& r3, uint32_t a) {
    asm volatile("ldmatrix.sync.aligned.m8n8.x4.trans.shared.b16 {%0,%1,%2,%3}, [%4];"
                 : "=r"(r0), "=r"(r1), "=r"(r2), "=r"(r3) : "r"(a));
}
__device__ __forceinline__ void mma_bf16(float* c, const uint32_t* a,
                                         uint32_t b0, uint32_t b1) {
    asm volatile(
        "mma.sync.aligned.m16n8k16.row.col.f32.bf16.bf16.f32 "
        "{%0,%1,%2,%3},{%4,%5,%6,%7},{%8,%9},{%0,%1,%2,%3};"
        : "+f"(c[0]), "+f"(c[1]), "+f"(c[2]), "+f"(c[3])
        : "r"(a[0]), "r"(a[1]), "r"(a[2]), "r"(a[3]), "r"(b0), "r"(b1));
}
__device__ __forceinline__ void cp16(uint32_t dst, const void* src) {
    asm volatile("cp.async.cg.shared.global [%0], [%1], 16;" :: "r"(dst), "l"(src));
}
__device__ __forceinline__ void cp_commit() {
    asm volatile("cp.async.commit_group;");
}
template <int N>
__device__ __forceinline__ void cp_wait() {
    asm volatile("cp.async.wait_group %0;" :: "n"(N));
}

// ---------------- conversion kernels ----------------------------------------
__global__ void kconv_w(const float* __restrict__ Wk, const float* __restrict__ Wq,
                        const float* __restrict__ Wd, const float* __restrict__ Wu)
{
    const size_t i = (size_t)blockIdx.x * blockDim.x + threadIdx.x;
    const size_t nw = 4ull * NL * NC;       // 524288
    if (i < nw) {
        g_wbf[0 * nw + i] = __float2bfloat16(Wk[i]);
        g_wbf[1 * nw + i] = __float2bfloat16(Wq[i]);
        g_wbf[2 * nw + i] = __float2bfloat16(Wd[i]);
        g_wubf[i]         = __float2bfloat16(Wu[i]);
    }
}

__global__ void kconv_x(const float* __restrict__ x0, const float* __restrict__ x1,
                        const float* __restrict__ x2, const float* __restrict__ x3)
{
    const int s = blockIdx.y;
    const float* xp = (s == 0) ? x0 : (s == 1) ? x1 : (s == 2) ? x2 : x3;
    __nv_bfloat16* dst = g_xbf + (size_t)s * NB * NC * NP;
    const size_t n4 = (size_t)NB * NC * NP / 4;
    for (size_t i = (size_t)blockIdx.x * blockDim.x + threadIdx.x;
         i < n4; i += (size_t)gridDim.x * blockDim.x) {
        float4 v = *(const float4*)(xp + i * 4);
        __nv_bfloat162 lo = __floats2bfloat162_rn(v.x, v.y);
        __nv_bfloat162 hi = __floats2bfloat162_rn(v.z, v.w);
        uint2 pk;
        pk.x = *(uint32_t*)&lo;
        pk.y = *(uint32_t*)&hi;
        *(uint2*)(dst + i * 4) = pk;
    }
}

// ---------------- Kernel P: projection GEMM (tensor core, 3-stage pipe) -----
// C[l 128 x p 128] = W[l x 512] * X[512 x p] for one (mat,s,b,ltile).
// grid (32 ptiles, 12 = mat*4+s, 16 = b*2+ltile), 256 threads (8 warps 2x4).
#define SA 40    // Wsm row stride (bf16), 32 + 8 pad
#define SB 136   // Xsm row stride (bf16), 128 + 8 pad
#define KP_WB (128 * SA)
#define KP_XB (32 * SB)
#define KP_SMEM ((3 * KP_WB + 3 * KP_XB) * 2)

__global__ __launch_bounds__(256)
void kp_proj(const float* __restrict__ bk,
             const float* __restrict__ gk, const float* __restrict__ betak,
             const float* __restrict__ mk, const float* __restrict__ vk,
             const float* __restrict__ bq,
             const float* __restrict__ gq, const float* __restrict__ betaq,
             const float* __restrict__ mq, const float* __restrict__ vq,
             const float* __restrict__ bd)
{
    extern __shared__ __nv_bfloat16 smp[];

    const int p0  = blockIdx.x * 128;
    const int mat = blockIdx.y >> 2;
    const int s   = blockIdx.y & 3;
    const int b   = blockIdx.z >> 1;
    const int l0  = (blockIdx.z & 1) * 128;
    const int tid = threadIdx.x;
    const int warp = tid >> 5, lane = tid & 31;
    const int wm = warp >> 2, wn = warp & 3;

    const __nv_bfloat16* wsrc = g_wbf + ((size_t)mat * 4 + s) * (NL * NC)
                                      + (size_t)l0 * NC;
    const __nv_bfloat16* xsrc = g_xbf + ((size_t)(s * NB + b)) * (NC * NP);

    // per-thread load coords (2 iters each of W and X)
    const int wl_row = tid >> 2,  wl_c8 = (tid & 3) * 8;   // W rows 0..63, +64
    const int xl_row = tid >> 4,  xl_p8 = (tid & 15) * 8;  // X rows 0..15, +16

    auto issue = [&](int chunk, int buf) {
        const int c0 = chunk * 32;
        __nv_bfloat16* Wb = smp + buf * KP_WB;
        __nv_bfloat16* Xb = smp + 3 * KP_WB + buf * KP_XB;
        cp16(smem_u32(Wb + wl_row * SA + wl_c8),
             wsrc + (size_t)wl_row * NC + c0 + wl_c8);
        cp16(smem_u32(Wb + (wl_row + 64) * SA + wl_c8),
             wsrc + (size_t)(wl_row + 64) * NC + c0 + wl_c8);
        cp16(smem_u32(Xb + xl_row * SB + xl_p8),
             xsrc + (size_t)(c0 + xl_row) * NP + p0 + xl_p8);
        cp16(smem_u32(Xb + (xl_row + 16) * SB + xl_p8),
             xsrc + (size_t)(c0 + xl_row + 16) * NP + p0 + xl_p8);
        cp_commit();
    };

    float acc[4][4][4];
    #pragma unroll
    for (int i = 0; i < 4; i++)
        #pragma unroll
        for (int j = 0; j < 4; j++)
            #pragma unroll
            for (int r = 0; r < 4; r++) acc[i][j][r] = 0.f;

    issue(0, 0);
    issue(1, 1);

    int bufc = 0;
    #pragma unroll 1
    for (int c = 0; c < 16; c++) {
        if (c < 14) { issue(c + 2, (bufc + 2) % 3); cp_wait<2>(); }
        else        { cp_wait<0>(); }
        __syncthreads();

        const uint32_t wbase = smem_u32(smp + bufc * KP_WB);
        const uint32_t xbase = smem_u32(smp + 3 * KP_WB + bufc * KP_XB);
        #pragma unroll
        for (int k0 = 0; k0 < 32; k0 += 16) {
            uint32_t a[4][4];
            #pragma unroll
            for (int mt = 0; mt < 4; mt++) {
                uint32_t addr = wbase +
                    ((wm * 64 + mt * 16 + (lane & 15)) * SA + k0 + ((lane & 16) >> 1)) * 2;
                ldsm_x4(a[mt][0], a[mt][1], a[mt][2], a[mt][3], addr);
            }
            uint32_t bb[4][2];
            #pragma unroll
            for (int ntp = 0; ntp < 2; ntp++) {
                uint32_t addr = xbase +
                    ((k0 + (lane & 15)) * SB + wn * 32 + ntp * 16 + ((lane & 16) >> 1)) * 2;
                uint32_t r0, r1, r2, r3;
                ldsm_x4t(r0, r1, r2, r3, addr);
                bb[ntp * 2 + 0][0] = r0; bb[ntp * 2 + 0][1] = r1;
                bb[ntp * 2 + 1][0] = r2; bb[ntp * 2 + 1][1] = r3;
            }
            #pragma unroll
            for (int mt = 0; mt < 4; mt++)
                #pragma unroll
                for (int nt = 0; nt < 4; nt++)
                    mma_bf16(acc[mt][nt], a[mt], bb[nt][0], bb[nt][1]);
        }
        __syncthreads();
        bufc = (bufc + 1) % 3;
    }

    // epilogue: BN/bias per l, write bf16 plane [l][p]
    __nv_bfloat16* plane = g_kqvb + (((size_t)(mat * 4 + s)) * NB + b) * PLANE;
    #pragma unroll
    for (int mt = 0; mt < 4; mt++)
        #pragma unroll
        for (int half = 0; half < 2; half++) {
            const int l  = l0 + wm * 64 + mt * 16 + (lane >> 2) + half * 8;
            const int sl = s * NL + l;
            float sc, sh;
            if (mat == 0) {
                sc = __ldg(gk + sl) * rsqrtf(__ldg(vk + sl) + BN_EPS);
                sh = __ldg(betak + sl) + (__ldg(bk + sl) - __ldg(mk + sl)) * sc;
            } else if (mat == 1) {
                sc = __ldg(gq + sl) * rsqrtf(__ldg(vq + sl) + BN_EPS);
                sh = __ldg(betaq + sl) + (__ldg(bq + sl) - __ldg(mq + sl)) * sc;
            } else {
                sc = 1.f;
                sh = __ldg(bd + sl);
            }
            #pragma unroll
            for (int nt = 0; nt < 4; nt++) {
                const int p = p0 + wn * 32 + nt * 8 + (lane & 3) * 2;
                float v0 = acc[mt][nt][half * 2 + 0];
                float v1 = acc[mt][nt][half * 2 + 1];
                v0 = fmaf(v0, sc, sh);
                v1 = fmaf(v1, sc, sh);
                if (mat < 2) { v0 = fmaxf(v0, 0.f); v1 = fmaxf(v1, 0.f); }
                __nv_bfloat162 pk = __floats2bfloat162_rn(v0, v1);
                *(uint32_t*)(plane + (size_t)l * NP + p) = *(uint32_t*)&pk;
            }
        }
}

// ---------------- Kernel A: per-position 4x4 stream attention ---------------
__global__ __launch_bounds__(256)
void ka_attn()
{
    const int b    = blockIdx.y;
    const int warp = threadIdx.x >> 5;
    const int lane = threadIdx.x & 31;
    const int r    = blockIdx.x * 8 + warp;

    float2 qv[4][4], kv[4][4], vv[4][4];
    #pragma unroll
    for (int s = 0; s < 4; s++) {
        const __nv_bfloat162* kb = (const __nv_bfloat162*)
            (g_kqvb + (((size_t)(0 * 4 + s)) * NB + b) * PLANE + (size_t)r * NL);
        const __nv_bfloat162* qb = (const __nv_bfloat162*)
            (g_kqvb + (((size_t)(1 * 4 + s)) * NB + b) * PLANE + (size_t)r * NL);
        const __nv_bfloat162* vb = (const __nv_bfloat162*)
            (g_kqvb + (((size_t)(2 * 4 + s)) * NB + b) * PLANE + (size_t)r * NL);
        #pragma unroll
        for (int e = 0; e < 4; e++) {
            kv[s][e] = __bfloat1622float2(kb[lane + e * 32]);
            qv[s][e] = __bfloat1622float2(qb[lane + e * 32]);
            vv[s][e] = __bfloat1622float2(vb[lane + e * 32]);
        }
    }
    float sim[4][4];
    #pragma unroll
    for (int s = 0; s < 4; s++)
        #pragma unroll
        for (int t = 0; t < 4; t++) {
            float p = 0.f;
            #pragma unroll
            for (int e = 0; e < 4; e++) {
                p = fmaf(qv[s][e].x, kv[t][e].x, p);
                p = fmaf(qv[s][e].y, kv[t][e].y, p);
            }
            #pragma unroll
            for (int off = 16; off > 0; off >>= 1)
                p += __shfl_xor_sync(0xffffffffu, p, off);
            sim[s][t] = p * SIM_SCALE;
        }
    float attn[4][4];
    #pragma unroll
    for (int s = 0; s < 4; s++) {
        float mx = fmaxf(fmaxf(sim[s][0], sim[s][1]), fmaxf(sim[s][2], sim[s][3]));
        float e0 = __expf(sim[s][0] - mx);
        float e1 = __expf(sim[s][1] - mx);
        float e2 = __expf(sim[s][2] - mx);
        float e3 = __expf(sim[s][3] - mx);
        float inv = 1.f / (e0 + e1 + e2 + e3);
        attn[s][0] = e0 * inv; attn[s][1] = e1 * inv;
        attn[s][2] = e2 * inv; attn[s][3] = e3 * inv;
    }
    #pragma unroll
    for (int s = 0; s < 4; s++) {
        __nv_bfloat162* dst = (__nv_bfloat162*)
            (g_ctxb + (((size_t)(s * NB + b)) * NP + r) * NL);
        #pragma unroll
        for (int e = 0; e < 4; e++) {
            float cx = attn[s][0] * vv[0][e].x + attn[s][1] * vv[1][e].x
                     + attn[s][2] * vv[2][e].x + attn[s][3] * vv[3][e].x;
            float cy = attn[s][0] * vv[0][e].y + attn[s][1] * vv[1][e].y
                     + attn[s][2] * vv[2][e].y + attn[s][3] * vv[3][e].y;
            dst[lane + e * 32] = __floats2bfloat162_rn(cx, cy);
        }
    }
}

// ---------------- Kernel U: up-projection + bias + residual (3-stage pipe) --
// grid (32 ptiles, 4 ctiles, 32 sb), 256 thr (8 warps 2x4).
#define SC 40
#define KU_TB (128 * SC)
#define KU_SMEM (6 * KU_TB * 2)

__global__ __launch_bounds__(256)
void ku_up(const float* __restrict__ x0, const float* __restrict__ x1,
           const float* __restrict__ x2, const float* __restrict__ x3,
           const float* __restrict__ bu, float* __restrict__ out)
{
    extern __shared__ __nv_bfloat16 smu[];

    const int sb = blockIdx.z;
    const int s  = sb >> 3;
    const int b  = sb & 7;
    const int c0b = blockIdx.y * 128;
    const int p0  = blockIdx.x * 128;
    const int tid = threadIdx.x;
    const int warp = tid >> 5, lane = tid & 31;
    const int wm = warp >> 2, wn = warp & 3;

    const __nv_bfloat16* wsrc = g_wubf + ((size_t)s * NC + c0b) * NL;
    const __nv_bfloat16* csrc = g_ctxb + ((size_t)sb * NP + p0) * NL;

    const int t_row = tid >> 2, t_m8 = (tid & 3) * 8;   // rows 0..63, +64

    auto issue = [&](int chunk, int buf) {
        const int m0 = chunk * 32;
        __nv_bfloat16* Wb = smu + buf * KU_TB;
        __nv_bfloat16* Cb = smu + 3 * KU_TB + buf * KU_TB;
        cp16(smem_u32(Wb + t_row * SC + t_m8),
             wsrc + (size_t)t_row * NL + m0 + t_m8);
        cp16(smem_u32(Wb + (t_row + 64) * SC + t_m8),
             wsrc + (size_t)(t_row + 64) * NL + m0 + t_m8);
        cp16(smem_u32(Cb + t_row * SC + t_m8),
             csrc + (size_t)t_row * NL + m0 + t_m8);
        cp16(smem_u32(Cb + (t_row + 64) * SC + t_m8),
             csrc + (size_t)(t_row + 64) * NL + m0 + t_m8);
        cp_commit();
    };

    float acc[4][4][4];
    #pragma unroll
    for (int i = 0; i < 4; i++)
        #pragma unroll
        for (int j = 0; j < 4; j++)
            #pragma unroll
            for (int r = 0; r < 4; r++) acc[i][j][r] = 0.f;

    issue(0, 0);
    issue(1, 1);

    int bufc = 0;
    #pragma unroll 1
    for (int c = 0; c < 8; c++) {
        if (c < 6) { issue(c + 2, (bufc + 2) % 3); cp_wait<2>(); }
        else       { cp_wait<0>(); }
        __syncthreads();

        const uint32_t wbase = smem_u32(smu + bufc * KU_TB);
        const uint32_t cbase = smem_u32(smu + 3 * KU_TB + bufc * KU_TB);
        #pragma unroll
        for (int k0 = 0; k0 < 32; k0 += 16) {
            uint32_t a[4][4];
            #pragma unroll
            for (int mt = 0; mt < 4; mt++) {
                uint32_t addr = wbase +
                    ((wm * 64 + mt * 16 + (lane & 15)) * SC + k0 + ((lane & 16) >> 1)) * 2;
                ldsm_x4(a[mt][0], a[mt][1], a[mt][2], a[mt][3], addr);
            }
            uint32_t bb[4][2];
            #pragma unroll
            for (int ntp = 0; ntp < 2; ntp++) {
                uint32_t addr = cbase +
                    ((wn * 32 + ntp * 16 + (lane & 7) + ((lane & 16) >> 1)) * SC
                     + k0 + (lane & 8)) * 2;
                uint32_t r0, r1, r2, r3;
                ldsm_x4(r0, r1, r2, r3, addr);
                bb[ntp * 2 + 0][0] = r0; bb[ntp * 2 + 0][1] = r1;
                bb[ntp * 2 + 1][0] = r2; bb[ntp * 2 + 1][1] = r3;
            }
            #pragma unroll
            for (int mt = 0; mt < 4; mt++)
                #pragma unroll
                for (int nt = 0; nt < 4; nt++)
                    mma_bf16(acc[mt][nt], a[mt], bb[nt][0], bb[nt][1]);
        }
        __syncthreads();
        bufc = (bufc + 1) % 3;
    }

    const float* xp = (s == 0) ? x0 : (s == 1) ? x1 : (s == 2) ? x2 : x3;
    #pragma unroll
    for (int mt = 0; mt < 4; mt++)
        #pragma unroll
        for (int half = 0; half < 2; half++) {
            const int c = c0b + wm * 64 + mt * 16 + (lane >> 2) + half * 8;
            const float bias = __ldg(bu + s * NC + c);
            const float* xrow = xp + ((size_t)b * NC + c) * NP + p0;
            float* orow = out + ((size_t)sb * NC + c) * NP + p0;
            #pragma unroll
            for (int nt = 0; nt < 4; nt++) {
                const int p = wn * 32 + nt * 8 + (lane & 3) * 2;
                float2 xv = *(const float2*)(xrow + p);
                float2 o;
                o.x = xv.x + bias + acc[mt][nt][half * 2 + 0];
                o.y = xv.y + bias + acc[mt][nt][half * 2 + 1];
                *(float2*)(orow + p) = o;
            }
        }
}

extern "C" void kernel_launch(void* const* d_in, const int* in_sizes, int n_in,
                              void* d_out, int out_size)
{
    const float* x0    = (const float*)d_in[0];
    const float* x1    = (const float*)d_in[1];
    const float* x2    = (const float*)d_in[2];
    const float* x3    = (const float*)d_in[3];
    const float* Wk    = (const float*)d_in[4];
    const float* bk    = (const float*)d_in[5];
    const float* gk    = (const float*)d_in[6];
    const float* betak = (const float*)d_in[7];
    const float* mk    = (const float*)d_in[8];
    const float* vk    = (const float*)d_in[9];
    const float* Wq    = (const float*)d_in[10];
    const float* bq    = (const float*)d_in[11];
    const float* gq    = (const float*)d_in[12];
    const float* betaq = (const float*)d_in[13];
    const float* mq    = (const float*)d_in[14];
    const float* vq    = (const float*)d_in[15];
    const float* Wd    = (const float*)d_in[16];
    const float* bd    = (const float*)d_in[17];
    const float* Wu    = (const float*)d_in[18];
    const float* bu    = (const float*)d_in[19];
    float* out = (float*)d_out;

    cudaFuncSetAttribute(kp_proj, cudaFuncAttributeMaxDynamicSharedMemorySize, KP_SMEM);
    cudaFuncSetAttribute(ku_up,   cudaFuncAttributeMaxDynamicSharedMemorySize, KU_SMEM);

    kconv_w<<<2048, 256>>>(Wk, Wq, Wd, Wu);
    kconv_x<<<dim3(4096, 4), 256>>>(x0, x1, x2, x3);
    kp_proj<<<dim3(32, 12, 16), 256, KP_SMEM>>>(bk, gk, betak, mk, vk,
                                                bq, gq, betaq, mq, vq, bd);
    ka_attn<<<dim3(512, 8), 256>>>();
    ku_up<<<dim3(32, 4, 32), 256, KU_SMEM>>>(x0, x1, x2, x3, bu, out);
}